// round 7
// baseline (speedup 1.0000x reference)
#include <cuda_runtime.h>
#include <math.h>

#define BSZ 2048
#define TT 8
#define NQ 10
#define SLOTS 4              // batch elements per block (2 warps each)
#define NTH 256              // 8 warps
#define NBLK (BSZ / SLOTS)
#define FULLM 0xffffffffu

__device__ __forceinline__ float fast_tanh(float x) {
    float y; asm("tanh.approx.f32 %0, %1;" : "=f"(y) : "f"(x)); return y;
}
__device__ __forceinline__ float fast_sigmoid(float x) {
    return 0.5f * fast_tanh(0.5f * x) + 0.5f;
}
__device__ __forceinline__ void pair_bar(int slot) {
    asm volatile("bar.sync %0, %1;" :: "r"(slot + 1), "r"(64) : "memory");
}

// circuits: sidx 0=forget(c0) 1=input(c1) 2=candidate(c3) 3=memory(c4) 4=temporal(c5)
__global__ __launch_bounds__(NTH, 4) void qlstm_kernel(
    const float* __restrict__ x, const float* __restrict__ Wx,
    const float* __restrict__ Wh, const float* __restrict__ bias,
    const float* __restrict__ R, float* __restrict__ out)
{
    __shared__ __align__(16) float sRT[5][NQ][32];   // sRT[sidx][n][f], f padded to 32
    __shared__ __align__(16) float sF[SLOTS][5][32]; // features, padded to 32
    __shared__ float sG[SLOTS][5][NQ];
    __shared__ float sH[SLOTS][NQ];

    const int tid = threadIdx.x, w = tid >> 5, lane = tid & 31;
    const int slot = w >> 1, sub = w & 1;
    const int b = blockIdx.x * SLOTS + slot;

    // ---- init: transposed, padded R for vectorized matmul ----
    {
        const int CMAPc[5] = {0, 1, 3, 4, 5};
        for (int i = tid; i < 5 * NQ * 32; i += NTH) {
            int sidx = i / 320, rem = i - sidx * 320, n = rem >> 5, f = rem & 31;
            sRT[sidx][n][f] = (f < 30) ? R[CMAPc[sidx] * 300 + f * 10 + n] : 0.f;
        }
        for (int i = tid; i < SLOTS * 5; i += NTH) {
            sF[i / 5][i % 5][30] = 0.f;
            sF[i / 5][i % 5][31] = 0.f;
        }
        if (tid < SLOTS * NQ) sH[tid / NQ][tid % NQ] = 0.f;
    }

    // ---- per-lane owned preactivation column + register weights ----
    int col;
    if (sub == 0) {
        col = (lane < 30) ? lane : 0;            // cols 0..29 (forget 0-9, input 10-29)
    } else {
        if (lane < 20)      col = 41 + 3 * (lane >> 1) + (lane & 1); // cand (3q+0 unused)
        else if (lane < 30) col = 50 + lane;     // memory 70..79
        else                col = 80;            // temporal
    }
    float wxr[NQ], whr[NQ];
    #pragma unroll
    for (int k = 0; k < NQ; k++) { wxr[k] = Wx[k * 81 + col]; whr[k] = Wh[k * 81 + col]; }
    const float bcol = bias[col];

    // circ_output is constant: feats=[0,1,0] per qubit -> G2[n] = sum_q R[2][3q+1][n]
    float G2 = 0.f;
    if (sub == 0 && lane < NQ) {
        #pragma unroll
        for (int q = 0; q < NQ; q++) G2 += R[600 + (3 * q + 1) * 10 + lane];
    }

    // shuffle source indices for stage 2 (computed once; uniform over t)
    int idxA, idxB;
    if (sub == 0) {
        idxA = (lane < 10) ? lane : ((lane < 20) ? (2 * lane - 10) : 0);
        idxB = (lane >= 10 && lane < 20) ? (2 * lane - 9) : 0;
    } else {
        idxA = (lane < 10) ? 2 * lane : ((lane < 20) ? (lane + 10) : 30);
        idxB = (lane < 10) ? (2 * lane + 1) : 30;
    }

    __syncthreads();

    float creg = 0.f;

    for (int t = 0; t < TT; t++) {
        pair_bar(slot);   // sH (and first-iter init) visible to both warps of the pair

        // ---- matvec: p_col = bias + x_t@Wx + h@Wh via register weights + shuffles ----
        float xv = 0.f, hv = 0.f;
        if (lane < NQ) {
            xv = x[(b * TT + t) * NQ + lane];
            hv = sH[slot][lane];
        }
        float p = bcol;
        #pragma unroll
        for (int k = 0; k < NQ; k++) {
            float xk = __shfl_sync(FULLM, xv, k);
            float hk = __shfl_sync(FULLM, hv, k);
            p = fmaf(xk, wxr[k], fmaf(hk, whr[k], p));
        }
        float pA = __shfl_sync(FULLM, p, idxA);
        float pB = __shfl_sync(FULLM, p, idxB);

        // ---- stage 2 + features, all in registers + subset shuffles ----
        float f0 = 0.f, f1 = 0.f, f2 = 0.f;
        int sidx, q;
        if (sub == 0) {
            if (lane < 10) {                       // forget: RY on uniform, then T + CZ pairs
                sidx = 0; q = lane;
                float sn, cs; __sincosf(pA, &sn, &cs);
                float pz = -sn, xr = 0.5f * cs;
                float pzn = __shfl_xor_sync(0x3FFu, pz, 1);
                f0 = pz;
                f1 = 1.41421356237f * xr * pzn;
                f2 = f1;
            } else if (lane < 20) {                // input: RZ*RY on uniform, CNOT chain
                sidx = 1; q = lane - 10;
                float s1, c1; __sincosf(pA, &s1, &c1);
                float s2, c2; __sincosf(pB, &s2, &c2);
                float pz = -s1, xr = 0.5f * c1 * c2, xi = 0.5f * c1 * s2;
                float incl = pz;
                #pragma unroll
                for (int d = 1; d < 10; d <<= 1) {
                    float tv = __shfl_up_sync(0xFFC00u, incl, d);
                    if (q >= d) incl *= tv;
                }
                float ex = __shfl_up_sync(0xFFC00u, incl, 1);
                if (q == 0) ex = 1.f;
                float xrn = __shfl_down_sync(0xFFC00u, xr, 1);
                float C = (q < 9) ? 2.f * xrn : 1.f;
                f0 = incl;
                f1 = 2.f * C * xr;
                f2 = 2.f * C * xi * ex;
            } else { sidx = 0; q = 0; }
        } else {
            if (lane < 10) {                       // candidate: RZ RY RZ H|0>, CAND_CZ
                sidx = 2; q = lane;
                float s1, c1; __sincosf(pA, &s1, &c1);
                float s2, c2; __sincosf(pB, &s2, &c2);
                float pz = c1, xr = 0.5f * s1 * c2, xi = 0.5f * s1 * s2;
                float prod = 1.f;
                const int MASK[10] = {0x304,0x48,0x2F9,0x86,0x44,0x204,0x16,0xC,0x1,0x25};
                #pragma unroll
                for (int j = 0; j < NQ; j++) {
                    float pj = __shfl_sync(0x3FFu, pz, j);
                    if ((MASK[j] >> q) & 1) prod *= pj;
                }
                f0 = pz; f1 = 2.f * xr * prod; f2 = 2.f * xi * prod;
            } else if (lane < 20) {                // memory: RY on uniform, CZ pairs
                sidx = 3; q = lane - 10;
                float sn, cs; __sincosf(pA, &sn, &cs);
                float pz = -sn, xr = 0.5f * cs;
                float pzn = __shfl_xor_sync(0xFFC00u, pz, 1);
                f0 = pz; f1 = 2.f * xr * pzn; f2 = 0.f;
            } else if (lane < 30) {                // temporal
                sidx = 4; q = lane - 20;
                float tp = pA;
                float a = 0.1f * tp, bb = 0.05f * tp;
                float SB, CB; __sincosf(0.5f * bb, &SB, &CB);
                float pz, xr, xi;
                if (q == 0) {                      // qubit 0 input |0>
                    pz = CB * CB - SB * SB; xr = 0.f; xi = -CB * SB;
                } else {                           // input |+>
                    float SA, CA; __sincosf(0.5f * a, &SA, &CA);
                    const float RS = 0.70710678118654752f;
                    float v0r = (CB*CA + SB*SA)*RS, v0i = -(CB*SA + SB*CA)*RS;
                    float v1r = (CB*CA - SB*SA)*RS, v1i = (CB*SA - SB*CA)*RS;
                    pz = v0r*v0r + v0i*v0i - v1r*v1r - v1i*v1i;
                    xr = v0r*v1r + v0i*v1i;
                    xi = v0r*v1i - v0i*v1r;
                }
                float s2z, c2z; __sincosf(0.2f * tp, &s2z, &c2z);
                float pzm = __shfl_up_sync(0x3FF00000u, pz, 1);
                float pzp = __shfl_down_sync(0x3FF00000u, pz, 1);
                float er = 1.f, ei = 0.f;
                if (q > 0) { er = c2z; ei = s2z * pzm; }
                if (q < 9) {
                    float fr = c2z, fi = s2z * pzp;
                    float nr = er * fr - ei * fi, ni = er * fi + ei * fr;
                    er = nr; ei = ni;
                }
                f0 = pz;
                f1 = 2.f * (xr * er - xi * ei);
                f2 = 2.f * (xr * ei + xi * er);
            } else { sidx = 2; q = 0; }
        }
        bool fact = (sub == 0) ? (lane < 20) : (lane < 30);
        if (fact) {
            sF[slot][sidx][3 * q]     = f0;
            sF[slot][sidx][3 * q + 1] = f1;
            sF[slot][sidx][3 * q + 2] = f2;
        }
        __syncwarp();

        // ---- gates = feats @ R  (vectorized LDS.128, one output per lane) ----
        {
            int nout = (sub == 0) ? 20 : 30;
            if (lane < nout) {
                int so = lane / 10, n = lane - so * 10;
                int si = (sub == 0) ? so : 2 + so;
                const float4* Fv = (const float4*)sF[slot][si];
                const float4* Rv = (const float4*)sRT[si][n];
                float4 a4 = make_float4(0.f, 0.f, 0.f, 0.f);
                #pragma unroll
                for (int i = 0; i < 8; i++) {
                    float4 fv = Fv[i], rv = Rv[i];
                    a4.x = fmaf(fv.x, rv.x, a4.x);
                    a4.y = fmaf(fv.y, rv.y, a4.y);
                    a4.z = fmaf(fv.z, rv.z, a4.z);
                    a4.w = fmaf(fv.w, rv.w, a4.w);
                }
                sG[slot][si][n] = (a4.x + a4.y) + (a4.z + a4.w);
            }
        }

        pair_bar(slot);   // sG complete for both warps

        // ---- LSTM cell update (sub 0, lanes 0..9) ----
        if (sub == 0 && lane < NQ) {
            float fg = fast_sigmoid(sG[slot][0][lane]);
            float ig = fast_sigmoid(sG[slot][1][lane]);
            float gg = fast_tanh(sG[slot][2][lane]);
            float mq = fast_sigmoid(sG[slot][3][lane]);
            float tm = fast_tanh(sG[slot][4][lane]);
            float og = fast_sigmoid(G2);
            float cn = (fg * creg + ig * gg) * mq;
            float hn = og * fast_tanh(cn) + 0.1f * tm;
            creg = cn;
            sH[slot][lane] = hn;
            out[(b * TT + t) * NQ + lane] = hn;
        }
    }
}

extern "C" void kernel_launch(void* const* d_in, const int* in_sizes, int n_in,
                              void* d_out, int out_size)
{
    const float* x    = (const float*)d_in[0];
    const float* Wx   = (const float*)d_in[1];
    const float* Wh   = (const float*)d_in[2];
    const float* bias = (const float*)d_in[3];
    const float* R    = (const float*)d_in[4];
    float* out = (float*)d_out;

    qlstm_kernel<<<NBLK, NTH>>>(x, Wx, Wh, bias, R, out);
}

// round 9
// speedup vs baseline: 2.2850x; 2.2850x over previous
#include <cuda_runtime.h>
#include <math.h>

#define BSZ 2048
#define TT 8
#define NQ 10
#define FULLM 0xffffffffu

__device__ __forceinline__ float fast_tanh(float x) {
    float y; asm("tanh.approx.f32 %0, %1;" : "=f"(y) : "f"(x)); return y;
}
__device__ __forceinline__ float fast_sigmoid(float x) {
    return 0.5f * fast_tanh(0.5f * x) + 0.5f;
}

// One warp per batch element. 2048 blocks x 32 threads.
__global__ __launch_bounds__(32, 14) void qlstm_kernel(
    const float* __restrict__ x, const float* __restrict__ Wx,
    const float* __restrict__ Wh, const float* __restrict__ bias,
    const float* __restrict__ R, float* __restrict__ out)
{
    __shared__ float sP[84];        // preactivation columns (only live cols used)
    __shared__ float sF[3][33];     // full features: 0=input 1=candidate 2=temporal (pad 33)
    __shared__ float sFsm[40];      // folded: [0..19]=forget, [20..39]=memory

    const int lane = threadIdx.x;
    const int b = blockIdx.x;

    // ---- matvec column ownership: colA = 0..29 | 80 ; colB = cand/mem cols ----
    int colA = (lane < 30) ? lane : 80;
    int colB;
    if (lane < 20)      colB = 41 + 3 * (lane >> 1) + (lane & 1);  // cand cols 41+3q,42+3q
    else if (lane < 30) colB = 50 + lane;                          // memory 70..79
    else                colB = 80;                                 // unused

    float wxA[NQ], whA[NQ], wxB[NQ], whB[NQ];
    #pragma unroll
    for (int k = 0; k < NQ; k++) {
        wxA[k] = Wx[k * 81 + colA];  whA[k] = Wh[k * 81 + colA];
        wxB[k] = Wx[k * 81 + colB];  whB[k] = Wh[k * 81 + colB];
    }
    const float bA = bias[colA], bB = bias[colB];

    // ---- gate-matmul weights in registers (per-lane fixed output column) ----
    const int n1 = lane % 10;
    float Rp1[20];                       // pass1: forget (lanes 0-9) / memory (10-19), folded
    if (lane < 10) {
        #pragma unroll
        for (int q = 0; q < NQ; q++) {
            Rp1[2*q]   = R[(3*q) * 10 + n1];
            Rp1[2*q+1] = R[(3*q+1) * 10 + n1] + R[(3*q+2) * 10 + n1];
        }
    } else if (lane < 20) {
        #pragma unroll
        for (int q = 0; q < NQ; q++) {
            Rp1[2*q]   = R[1200 + (3*q) * 10 + n1];
            Rp1[2*q+1] = R[1200 + (3*q+1) * 10 + n1];
        }
    } else {
        #pragma unroll
        for (int f = 0; f < 20; f++) Rp1[f] = 0.f;
    }
    float Rp2[30];                       // pass2: input / candidate / temporal (full 30)
    if (lane < 30) {
        int g = lane / 10;
        int base = ((g == 0) ? 1 : ((g == 1) ? 3 : 5)) * 300;
        #pragma unroll
        for (int f = 0; f < 30; f++) Rp2[f] = R[base + f * 10 + n1];
    } else {
        #pragma unroll
        for (int f = 0; f < 30; f++) Rp2[f] = 0.f;
    }

    // circ_output is constant -> og fixed for the whole sequence
    float og = 0.f;
    if (lane < NQ) {
        float G2 = 0.f;
        #pragma unroll
        for (int q = 0; q < NQ; q++) G2 += R[600 + (3*q+1) * 10 + lane];
        og = fast_sigmoid(G2);
    }

    float hv = 0.f, creg = 0.f;

    for (int t = 0; t < TT; t++) {
        float xv = (lane < NQ) ? x[(b * TT + t) * NQ + lane] : 0.f;

        // ---- matvec: 2 register-weight chains + x/h shuffle broadcast ----
        float pA = bA, pB = bB;
        #pragma unroll
        for (int k = 0; k < NQ; k++) {
            float xk = __shfl_sync(FULLM, xv, k);
            float hk = __shfl_sync(FULLM, hv, k);
            pA = fmaf(xk, wxA[k], fmaf(hk, whA[k], pA));
            pB = fmaf(xk, wxB[k], fmaf(hk, whB[k], pB));
        }
        if (lane < 31) sP[colA] = pA;
        if (lane < 30) sP[colB] = pB;
        __syncwarp();

        // ---- stage 2 pass 1: forget / input / candidate ----
        if (lane < 10) {                       // forget: RY on uniform; T + CZ pairs (folded)
            float sn, cs; __sincosf(sP[lane], &sn, &cs);
            float pz = -sn, xr = 0.5f * cs;
            float pzn = __shfl_xor_sync(0x3FFu, pz, 1);
            sFsm[2*lane]   = pz;
            sFsm[2*lane+1] = 1.41421356237f * xr * pzn;
        } else if (lane < 20) {                // input: RZ*RY on uniform; CNOT chain
            int q = lane - 10;
            float s1, c1; __sincosf(sP[10 + 2*q], &s1, &c1);
            float s2, c2; __sincosf(sP[11 + 2*q], &s2, &c2);
            float pz = -s1, xr = 0.5f * c1 * c2, xi = 0.5f * c1 * s2;
            float incl = pz;
            #pragma unroll
            for (int d = 1; d < 10; d <<= 1) {
                float tv = __shfl_up_sync(0xFFC00u, incl, d);
                if (q >= d) incl *= tv;
            }
            float ex = __shfl_up_sync(0xFFC00u, incl, 1);
            if (q == 0) ex = 1.f;
            float xrn = __shfl_down_sync(0xFFC00u, xr, 1);
            float C = (q < 9) ? 2.f * xrn : 1.f;
            sF[0][3*q]   = incl;
            sF[0][3*q+1] = 2.f * C * xr;
            sF[0][3*q+2] = 2.f * C * xi * ex;
        } else if (lane < 30) {                // candidate: RZ RY RZ H|0>; CAND_CZ
            int q = lane - 20;
            float s1, c1; __sincosf(sP[41 + 3*q], &s1, &c1);
            float s2, c2; __sincosf(sP[42 + 3*q], &s2, &c2);
            float pz = c1, xr = 0.5f * s1 * c2, xi = 0.5f * s1 * s2;
            const int MASK[10] = {0x304,0x48,0x2F9,0x86,0x44,0x204,0x16,0xC,0x1,0x25};
            float prod = 1.f;
            #pragma unroll
            for (int j = 0; j < NQ; j++) {
                float pj = __shfl_sync(0x3FF00000u, pz, 20 + j);
                if ((MASK[j] >> q) & 1) prod *= pj;
            }
            sF[1][3*q]   = pz;
            sF[1][3*q+1] = 2.f * xr * prod;
            sF[1][3*q+2] = 2.f * xi * prod;
        }

        // ---- stage 2 pass 2: memory / temporal ----
        if (lane < 10) {                       // memory: RY on uniform; CZ pairs (folded)
            float sn, cs; __sincosf(sP[70 + lane], &sn, &cs);
            float pz = -sn, xr = 0.5f * cs;
            float pzn = __shfl_xor_sync(0x3FFu, pz, 1);
            sFsm[20 + 2*lane] = pz;
            sFsm[21 + 2*lane] = 2.f * xr * pzn;
        } else if (lane < 20) {                // temporal: RX(0.05t)*RZ(0.1t); ZZ sandwich
            int q = lane - 10;
            float tp = sP[80];
            float a = 0.1f * tp, bb = 0.05f * tp;
            float SB, CB; __sincosf(0.5f * bb, &SB, &CB);
            float pz, xr, xi;
            if (q == 0) {                      // qubit 0 input |0>
                pz = CB*CB - SB*SB; xr = 0.f; xi = -CB*SB;
            } else {                           // input |+>
                float SA, CA; __sincosf(0.5f * a, &SA, &CA);
                const float RS = 0.70710678118654752f;
                float v0r = (CB*CA + SB*SA)*RS, v0i = -(CB*SA + SB*CA)*RS;
                float v1r = (CB*CA - SB*SA)*RS, v1i = (CB*SA - SB*CA)*RS;
                pz = v0r*v0r + v0i*v0i - v1r*v1r - v1i*v1i;
                xr = v0r*v1r + v0i*v1i;
                xi = v0r*v1i - v0i*v1r;
            }
            float s2z, c2z; __sincosf(0.2f * tp, &s2z, &c2z);
            float pzm = __shfl_up_sync(0xFFC00u, pz, 1);
            float pzp = __shfl_down_sync(0xFFC00u, pz, 1);
            float er = 1.f, ei = 0.f;
            if (q > 0) { er = c2z; ei = s2z * pzm; }
            if (q < 9) {
                float fr = c2z, fi = s2z * pzp;
                float nr = er*fr - ei*fi, ni = er*fi + ei*fr;
                er = nr; ei = ni;
            }
            sF[2][3*q]   = pz;
            sF[2][3*q+1] = 2.f * (xr*er - xi*ei);
            sF[2][3*q+2] = 2.f * (xr*ei + xi*er);
        }
        __syncwarp();

        // ---- gates: register-R, smem-broadcast features ----
        float gp1 = 0.f, gp2 = 0.f;
        if (lane < 20) {                       // forget / memory (20 folded features)
            const float* Fp = sFsm + ((lane < 10) ? 0 : 20);
            #pragma unroll
            for (int f = 0; f < 20; f++) gp1 = fmaf(Fp[f], Rp1[f], gp1);
        }
        if (lane < 30) {                       // input / candidate / temporal (30 features)
            const float* Fq = sF[lane / 10];
            #pragma unroll
            for (int f = 0; f < 30; f++) gp2 = fmaf(Fq[f], Rp2[f], gp2);
        }

        // gather gates to lanes 0..9 and update
        float mqv = __shfl_sync(FULLM, gp1, lane + 10);
        float ggv = __shfl_sync(FULLM, gp2, lane + 10);
        float tmv = __shfl_sync(FULLM, gp2, lane + 20);
        if (lane < NQ) {
            float fg = fast_sigmoid(gp1);
            float ig = fast_sigmoid(gp2);
            float mq = fast_sigmoid(mqv);
            float gg = fast_tanh(ggv);
            float tm = fast_tanh(tmv);
            float cn = (fg * creg + ig * gg) * mq;
            float hn = og * fast_tanh(cn) + 0.1f * tm;
            creg = cn;
            hv = hn;
            out[(b * TT + t) * NQ + lane] = hn;
        }
        __syncwarp();
    }
}

extern "C" void kernel_launch(void* const* d_in, const int* in_sizes, int n_in,
                              void* d_out, int out_size)
{
    const float* x    = (const float*)d_in[0];
    const float* Wx   = (const float*)d_in[1];
    const float* Wh   = (const float*)d_in[2];
    const float* bias = (const float*)d_in[3];
    const float* R    = (const float*)d_in[4];
    float* out = (float*)d_out;

    qlstm_kernel<<<BSZ, 32>>>(x, Wx, Wh, bias, R, out);
}

// round 10
// speedup vs baseline: 2.7178x; 1.1894x over previous
#include <cuda_runtime.h>
#include <math.h>

#define BSZ 2048
#define TT 8
#define NQ 10
#define FULLM 0xffffffffu

__device__ __forceinline__ float fast_tanh(float x) {
    float y; asm("tanh.approx.f32 %0, %1;" : "=f"(y) : "f"(x)); return y;
}
__device__ __forceinline__ float fast_sigmoid(float x) {
    return 0.5f * fast_tanh(0.5f * x) + 0.5f;
}

// One warp per batch element. 2048 blocks x 32 threads.
// Shared feature layout (floats, 16B-aligned bases, banks disjoint per LDS.128 phase):
//   [  0.. 35] input features (30 + pad)
//   [ 36.. 71] candidate features
//   [ 72..107] temporal features
//   [108..127] forget folded (20)
//   [132..151] memory folded (20)
__global__ __launch_bounds__(32, 14) void qlstm_kernel(
    const float* __restrict__ x, const float* __restrict__ Wx,
    const float* __restrict__ Wh, const float* __restrict__ bias,
    const float* __restrict__ R, float* __restrict__ out)
{
    __shared__ __align__(16) float sAll[156];
    __shared__ float sPx[2][TT][32];

    const int lane = threadIdx.x;
    const int b = blockIdx.x;

    for (int i = lane; i < 156; i += 32) sAll[i] = 0.f;   // zero pads once

    // ---- matvec column ownership ----
    int colA = (lane < 30) ? lane : 80;                   // 0..29 | temporal(80)
    int colB;
    if (lane < 20)      colB = 41 + 3 * (lane >> 1) + (lane & 1);  // candidate
    else if (lane < 30) colB = 50 + lane;                          // memory 70..79
    else                colB = 80;

    float wxA[NQ], whA[NQ], wxB[NQ], whB[NQ];
    #pragma unroll
    for (int k = 0; k < NQ; k++) {
        wxA[k] = Wx[k*81 + colA];  whA[k] = Wh[k*81 + colA];
        wxB[k] = Wx[k*81 + colB];  whB[k] = Wh[k*81 + colB];
    }
    const float bA = bias[colA], bB = bias[colB];

    // ---- gate weights in registers ----
    const int n1 = lane % 10;
    float Rp1[20];
    if (lane < 10) {            // forget, folded (f1=f2)
        #pragma unroll
        for (int q = 0; q < NQ; q++) {
            Rp1[2*q]   = R[(3*q)*10 + n1];
            Rp1[2*q+1] = R[(3*q+1)*10 + n1] + R[(3*q+2)*10 + n1];
        }
    } else if (lane < 20) {     // memory, folded (f2=0)
        #pragma unroll
        for (int q = 0; q < NQ; q++) {
            Rp1[2*q]   = R[1200 + (3*q)*10 + n1];
            Rp1[2*q+1] = R[1200 + (3*q+1)*10 + n1];
        }
    } else {
        #pragma unroll
        for (int f = 0; f < 20; f++) Rp1[f] = 0.f;
    }
    float Rp2[32];
    Rp2[30] = 0.f; Rp2[31] = 0.f;
    if (lane < 30) {            // input / candidate / temporal
        int g = lane / 10;
        int base = ((g == 0) ? 1 : ((g == 1) ? 3 : 5)) * 300;
        #pragma unroll
        for (int f = 0; f < 30; f++) Rp2[f] = R[base + f*10 + n1];
    } else {
        #pragma unroll
        for (int f = 0; f < 30; f++) Rp2[f] = 0.f;
    }

    // circ_output constant -> og fixed
    float og = 0.f;
    if (lane < NQ) {
        float G2 = 0.f;
        #pragma unroll
        for (int q = 0; q < NQ; q++) G2 += R[600 + (3*q+1)*10 + lane];
        og = fast_sigmoid(G2);
    }

    // ---- precompute bias + x_t @ Wx for all timesteps (no h dependence) ----
    #pragma unroll
    for (int t = 0; t < TT; t++) {
        float xv = (lane < NQ) ? x[(b*TT + t)*NQ + lane] : 0.f;
        float a = bA, c2 = bB;
        #pragma unroll
        for (int k = 0; k < NQ; k++) {
            float xk = __shfl_sync(FULLM, xv, k);
            a  = fmaf(xk, wxA[k], a);
            c2 = fmaf(xk, wxB[k], c2);
        }
        sPx[0][t][lane] = a;
        sPx[1][t][lane] = c2;
    }
    __syncwarp();

    // ---- per-lane shuffle source indices (constant over t) ----
    const bool g0 = lane < 10, g1 = (lane >= 10 && lane < 20), g2 = (lane >= 20 && lane < 30);
    const int iA1 = g1 ? 2*lane - 10 : 0;       // input col 10+2q
    const int iA2 = g1 ? 2*lane - 9  : 0;       // input col 11+2q
    const int iB1 = g0 ? 20 + lane : (g2 ? 2*lane - 40 : 0);  // mem col / cand col1
    const int iB2 = g2 ? 2*lane - 39 : 0;                     // cand col2

    float hv = 0.f, creg = 0.f;

    for (int t = 0; t < TT; t++) {
        // ---- in-loop matvec: only h @ Wh remains ----
        float pA = sPx[0][t][lane], pB = sPx[1][t][lane];
        #pragma unroll
        for (int k = 0; k < NQ; k++) {
            float hk = __shfl_sync(FULLM, hv, k);
            pA = fmaf(hk, whA[k], pA);
            pB = fmaf(hk, whB[k], pB);
        }
        float a1 = __shfl_sync(FULLM, pA, iA1);
        float a2 = __shfl_sync(FULLM, pA, iA2);
        float b1 = __shfl_sync(FULLM, pB, iB1);
        float b2v = __shfl_sync(FULLM, pB, iB2);
        float tp = __shfl_sync(FULLM, pA, 30);

        // ---- stage 2: circuit features (fused single divergence tree) ----
        if (g0) {
            // forget: RY on uniform; T + CZ pairs (folded f1=f2)
            float sn, cs; __sincosf(pA, &sn, &cs);
            float pz = -sn, xr = 0.5f * cs;
            float pzn = __shfl_xor_sync(0x3FFu, pz, 1);
            sAll[108 + 2*lane] = pz;
            sAll[109 + 2*lane] = 1.41421356237f * xr * pzn;
            // memory: RY on uniform; CZ pairs (folded f2=0)
            float sn2, cs2; __sincosf(b1, &sn2, &cs2);
            float pz2 = -sn2, xr2 = 0.5f * cs2;
            float pzn2 = __shfl_xor_sync(0x3FFu, pz2, 1);
            sAll[132 + 2*lane] = pz2;
            sAll[133 + 2*lane] = 2.f * xr2 * pzn2;
        } else if (g1) {
            int q = lane - 10;
            // input: RZ*RY on uniform; CNOT chain
            float s1, c1; __sincosf(a1, &s1, &c1);
            float s2, c2; __sincosf(a2, &s2, &c2);
            float pz = -s1, xr = 0.5f*c1*c2, xi = 0.5f*c1*s2;
            float incl = pz;
            #pragma unroll
            for (int d = 1; d < 10; d <<= 1) {
                float tv = __shfl_up_sync(0xFFC00u, incl, d);
                if (q >= d) incl *= tv;
            }
            float ex = __shfl_up_sync(0xFFC00u, incl, 1);
            if (q == 0) ex = 1.f;
            float xrn = __shfl_down_sync(0xFFC00u, xr, 1);
            float C = (q < 9) ? 2.f * xrn : 1.f;
            sAll[3*q]   = incl;
            sAll[3*q+1] = 2.f * C * xr;
            sAll[3*q+2] = 2.f * C * xi * ex;
            // temporal: RX(0.05t)*RZ(0.1t); ZZ sandwich
            float a = 0.1f * tp, bb = 0.05f * tp;
            float SB, CB; __sincosf(0.5f * bb, &SB, &CB);
            float pzT, xrT, xiT;
            if (q == 0) {                      // qubit 0 in |0>
                pzT = CB*CB - SB*SB; xrT = 0.f; xiT = -CB*SB;
            } else {                           // |+> input
                float SA, CA; __sincosf(0.5f * a, &SA, &CA);
                const float RS = 0.70710678118654752f;
                float v0r = (CB*CA + SB*SA)*RS, v0i = -(CB*SA + SB*CA)*RS;
                float v1r = (CB*CA - SB*SA)*RS, v1i = (CB*SA - SB*CA)*RS;
                pzT = v0r*v0r + v0i*v0i - v1r*v1r - v1i*v1i;
                xrT = v0r*v1r + v0i*v1i;
                xiT = v0r*v1i - v0i*v1r;
            }
            float s2z, c2z; __sincosf(0.2f * tp, &s2z, &c2z);
            float pzm = __shfl_up_sync(0xFFC00u, pzT, 1);
            float pzp = __shfl_down_sync(0xFFC00u, pzT, 1);
            float er = 1.f, ei = 0.f;
            if (q > 0) { er = c2z; ei = s2z * pzm; }
            if (q < 9) {
                float fr = c2z, fi = s2z * pzp;
                float nr = er*fr - ei*fi, ni = er*fi + ei*fr;
                er = nr; ei = ni;
            }
            sAll[72 + 3*q]   = pzT;
            sAll[73 + 3*q]   = 2.f * (xrT*er - xiT*ei);
            sAll[74 + 3*q]   = 2.f * (xrT*ei + xiT*er);
        } else if (g2) {
            // candidate: RZ RY RZ H|0>; CAND_CZ
            int q = lane - 20;
            float s1, c1; __sincosf(b1, &s1, &c1);
            float s2, c2; __sincosf(b2v, &s2, &c2);
            float pz = c1, xr = 0.5f*s1*c2, xi = 0.5f*s1*s2;
            const int MASK[10] = {0x304,0x48,0x2F9,0x86,0x44,0x204,0x16,0xC,0x1,0x25};
            float prod = 1.f;
            #pragma unroll
            for (int j = 0; j < NQ; j++) {
                float pj = __shfl_sync(0x3FF00000u, pz, 20 + j);
                if ((MASK[j] >> q) & 1) prod *= pj;
            }
            sAll[36 + 3*q] = pz;
            sAll[37 + 3*q] = 2.f * xr * prod;
            sAll[38 + 3*q] = 2.f * xi * prod;
        }
        __syncwarp();

        // ---- gates: LDS.128 broadcasts + register R, 4-way accumulators ----
        float4 A1 = make_float4(0.f, 0.f, 0.f, 0.f);
        {
            const float4* F1 = (const float4*)(sAll + (g0 ? 108 : 132));
            #pragma unroll
            for (int i = 0; i < 5; i++) {
                float4 fv = F1[i];
                A1.x = fmaf(fv.x, Rp1[4*i],   A1.x);
                A1.y = fmaf(fv.y, Rp1[4*i+1], A1.y);
                A1.z = fmaf(fv.z, Rp1[4*i+2], A1.z);
                A1.w = fmaf(fv.w, Rp1[4*i+3], A1.w);
            }
        }
        float gp1 = (A1.x + A1.y) + (A1.z + A1.w);

        float4 A2 = make_float4(0.f, 0.f, 0.f, 0.f);
        {
            int gidx = (lane < 30) ? lane / 10 : 0;
            const float4* F2 = (const float4*)(sAll + 36*gidx);
            #pragma unroll
            for (int i = 0; i < 8; i++) {
                float4 fv = F2[i];
                A2.x = fmaf(fv.x, Rp2[4*i],   A2.x);
                A2.y = fmaf(fv.y, Rp2[4*i+1], A2.y);
                A2.z = fmaf(fv.z, Rp2[4*i+2], A2.z);
                A2.w = fmaf(fv.w, Rp2[4*i+3], A2.w);
            }
        }
        float gp2 = (A2.x + A2.y) + (A2.z + A2.w);

        // ---- gather gates to lanes 0..9, update cell ----
        float mqv = __shfl_sync(FULLM, gp1, lane + 10);
        float ggv = __shfl_sync(FULLM, gp2, lane + 10);
        float tmv = __shfl_sync(FULLM, gp2, lane + 20);
        float hn = 0.f;
        if (lane < NQ) {
            float fg = fast_sigmoid(gp1);
            float ig = fast_sigmoid(gp2);
            float mq = fast_sigmoid(mqv);
            float gg = fast_tanh(ggv);
            float tm = fast_tanh(tmv);
            float cn = (fg * creg + ig * gg) * mq;
            hn = og * fast_tanh(cn) + 0.1f * tm;
            creg = cn;
            out[(b*TT + t)*NQ + lane] = hn;
        }
        hv = hn;
    }
}

extern "C" void kernel_launch(void* const* d_in, const int* in_sizes, int n_in,
                              void* d_out, int out_size)
{
    const float* x    = (const float*)d_in[0];
    const float* Wx   = (const float*)d_in[1];
    const float* Wh   = (const float*)d_in[2];
    const float* bias = (const float*)d_in[3];
    const float* R    = (const float*)d_in[4];
    float* out = (float*)d_out;

    qlstm_kernel<<<BSZ, 32>>>(x, Wx, Wh, bias, R, out);
}